// round 2
// baseline (speedup 1.0000x reference)
#include <cuda_runtime.h>
#include <cuda_bf16.h>
#include <math.h>

#define N_NODES 10000
#define N_EDGES 160000
#define H 128
#define E_RBF 20
#define CUTOFF 5.0f
#define PI_F 3.14159265358979f

// ---------------- scratch (static device arrays; no allocation) ----------------
__device__ float g_ns[N_NODES * H];          // node scalar
__device__ float g_nvA[N_NODES * 3 * H];     // node vector (read copy)
__device__ float g_nvB[N_NODES * 3 * H];     // node vector (accumulate copy)
__device__ float g_hidden[N_NODES * H];      // hidden activations
__device__ float g_big[N_NODES * 3 * H];     // scalar_out / mlp_out (N x 384)
__device__ float g_Uv[N_NODES * 3 * H];
__device__ float g_Vv[N_NODES * 3 * H];
__device__ float g_mlpin[N_NODES * 2 * H];

// ---------------- helpers ----------------
__device__ __forceinline__ void red4(float* p, float4 v) {
    asm volatile("red.global.add.v4.f32 [%0], {%1,%2,%3,%4};"
                 :: "l"(p), "f"(v.x), "f"(v.y), "f"(v.z), "f"(v.w) : "memory");
}
__device__ __forceinline__ float4 f4fma(float a, float4 b, float4 c) {
    c.x = fmaf(a, b.x, c.x); c.y = fmaf(a, b.y, c.y);
    c.z = fmaf(a, b.z, c.z); c.w = fmaf(a, b.w, c.w);
    return c;
}
__device__ __forceinline__ float silu_f(float x) {
    return x / (1.0f + expf(-x));
}

// ---------------- init: ns = embed[z], nvA = nvB = 0 ----------------
__global__ void init_kernel(const int* __restrict__ z, const float* __restrict__ embed) {
    int i = blockIdx.x * blockDim.x + threadIdx.x;
    if (i >= N_NODES * 3 * H) return;
    g_nvA[i] = 0.0f;
    g_nvB[i] = 0.0f;
    if (i < N_NODES * H) {
        int n = i >> 7, h = i & 127;
        g_ns[i] = embed[z[n] * H + h];
    }
}

// ---------------- tiled fp32 GEMM: C = act(A[MxK] @ B[KxN] + bias) ----------------
// BM=128, BN=64, BK=16, 256 threads, 8x4 per thread. N % 64 == 0, K % 16 == 0.
template<bool SILU>
__global__ __launch_bounds__(256)
void sgemm_kernel(const float* __restrict__ A, const float* __restrict__ B,
                  const float* __restrict__ bias, float* __restrict__ C,
                  int M, int N, int K) {
    __shared__ float As[16][128];
    __shared__ float Bs[16][64];
    const int m0 = blockIdx.y * 128;
    const int n0 = blockIdx.x * 64;
    const int t  = threadIdx.x;
    const int tx = t & 15;       // 0..15 -> 4 cols
    const int ty = t >> 4;       // 0..15 -> 8 rows
    float acc[8][4];
#pragma unroll
    for (int i = 0; i < 8; i++)
#pragma unroll
        for (int j = 0; j < 4; j++) acc[i][j] = 0.0f;

    for (int k0 = 0; k0 < K; k0 += 16) {
        // load A tile (128x16), store transposed As[k][m]
#pragma unroll
        for (int i = 0; i < 2; i++) {
            int s  = t * 2 + i;           // 0..511
            int m  = s >> 2;              // 0..127
            int kq = s & 3;               // 0..3 (float4 along K)
            float4 v = make_float4(0.f, 0.f, 0.f, 0.f);
            if (m0 + m < M)
                v = *(const float4*)(A + (size_t)(m0 + m) * K + k0 + 4 * kq);
            As[4 * kq + 0][m] = v.x;
            As[4 * kq + 1][m] = v.y;
            As[4 * kq + 2][m] = v.z;
            As[4 * kq + 3][m] = v.w;
        }
        // load B tile (16x64)
        {
            int kk = t >> 4, n4 = t & 15;
            *(float4*)&Bs[kk][4 * n4] =
                *(const float4*)(B + (size_t)(k0 + kk) * N + n0 + 4 * n4);
        }
        __syncthreads();
#pragma unroll
        for (int k = 0; k < 16; k++) {
            float4 b4 = *(const float4*)&Bs[k][tx << 2];
            float a[8];
            *(float4*)&a[0] = *(const float4*)&As[k][ty * 8];
            *(float4*)&a[4] = *(const float4*)&As[k][ty * 8 + 4];
#pragma unroll
            for (int i = 0; i < 8; i++) {
                acc[i][0] = fmaf(a[i], b4.x, acc[i][0]);
                acc[i][1] = fmaf(a[i], b4.y, acc[i][1]);
                acc[i][2] = fmaf(a[i], b4.z, acc[i][2]);
                acc[i][3] = fmaf(a[i], b4.w, acc[i][3]);
            }
        }
        __syncthreads();
    }
    float4 bb = *(const float4*)&bias[n0 + (tx << 2)];
#pragma unroll
    for (int i = 0; i < 8; i++) {
        int m = m0 + ty * 8 + i;
        if (m < M) {
            float4 c;
            c.x = acc[i][0] + bb.x;
            c.y = acc[i][1] + bb.y;
            c.z = acc[i][2] + bb.z;
            c.w = acc[i][3] + bb.w;
            if (SILU) {
                c.x = silu_f(c.x); c.y = silu_f(c.y);
                c.z = silu_f(c.z); c.w = silu_f(c.w);
            }
            *(float4*)(C + (size_t)m * N + n0 + (tx << 2)) = c;
        }
    }
}

// ---------------- edge message kernel ----------------
// Per edge e: filter_w = (rbf @ Wf + bf) * fcut  (384),
//   fo = filter_w * scalar_out[src]; split into gate_sv/gate_ev/msg_s (128 each)
//   red-add msg_s -> ns[dst]; red-add nv_r[src]*gate_sv + unit*gate_ev -> nv_acc[dst]
// Warp per 2 edges; Wf staged in smem; rbf via sin(nx) recurrence.
__global__ __launch_bounds__(256)
void edge_kernel(const int* __restrict__ edge,
                 const float* __restrict__ ediff,
                 const float* __restrict__ edist,
                 const float* __restrict__ Wf,   // 20x384
                 const float* __restrict__ bf,   // 384
                 const float* __restrict__ so,   // N x 384 scalar_out
                 const float* __restrict__ nv_r, // N x 384 (read)
                 float* __restrict__ ns_acc,     // N x 128
                 float* __restrict__ nv_acc)     // N x 384
{
    __shared__ float sW[E_RBF * 384];
    __shared__ float sB[384];
    for (int i = threadIdx.x; i < E_RBF * 384; i += blockDim.x) sW[i] = Wf[i];
    for (int i = threadIdx.x; i < 384; i += blockDim.x) sB[i] = bf[i];
    __syncthreads();
    const float4* sW4 = (const float4*)sW;
    const float4* sB4 = (const float4*)sB;

    const int lane = threadIdx.x & 31;
    const int warp = (blockIdx.x * blockDim.x + threadIdx.x) >> 5;
    const int nw   = (gridDim.x * blockDim.x) >> 5;

    for (int e0 = warp * 2; e0 < N_EDGES; e0 += nw * 2) {
        int dst[2], src[2];
        float inv[2], fc[2], sC[2], sP[2], c2[2];
        float4 a0[2], a1[2], a2[2];
#pragma unroll
        for (int u = 0; u < 2; u++) {
            int e = e0 + u;
            dst[u] = edge[2 * e];
            src[u] = edge[2 * e + 1];
            float d = edist[e];
            float x = d * (PI_F / CUTOFF);
            float sn, cs;
            sincosf(x, &sn, &cs);
            inv[u] = 1.0f / d;
            fc[u]  = (d < CUTOFF) ? 0.5f * (cs + 1.0f) : 0.0f;
            sC[u] = sn; sP[u] = 0.0f; c2[u] = 2.0f * cs;
            a0[u] = sB4[lane];
            a1[u] = sB4[32 + lane];
            a2[u] = sB4[64 + lane];
        }
#pragma unroll
        for (int n = 0; n < E_RBF; n++) {
            float4 w0 = sW4[n * 96 + lane];
            float4 w1 = sW4[n * 96 + 32 + lane];
            float4 w2 = sW4[n * 96 + 64 + lane];
#pragma unroll
            for (int u = 0; u < 2; u++) {
                float r = sC[u] * inv[u];                  // rbf_n = sin(n x)/d
                a0[u] = f4fma(r, w0, a0[u]);
                a1[u] = f4fma(r, w1, a1[u]);
                a2[u] = f4fma(r, w2, a2[u]);
                float tn = c2[u] * sC[u] - sP[u];          // sin((n+1)x)
                sP[u] = sC[u]; sC[u] = tn;
            }
        }
#pragma unroll
        for (int u = 0; u < 2; u++) {
            int e = e0 + u;
            const float4* so4 = (const float4*)(so + (size_t)src[u] * 384);
            float f = fc[u];
            float4 s0 = so4[lane], s1 = so4[32 + lane], s2 = so4[64 + lane];
            float4 gsv, gev, ms;
            gsv.x = a0[u].x * f * s0.x; gsv.y = a0[u].y * f * s0.y;
            gsv.z = a0[u].z * f * s0.z; gsv.w = a0[u].w * f * s0.w;
            gev.x = a1[u].x * f * s1.x; gev.y = a1[u].y * f * s1.y;
            gev.z = a1[u].z * f * s1.z; gev.w = a1[u].w * f * s1.w;
            ms.x  = a2[u].x * f * s2.x; ms.y  = a2[u].y * f * s2.y;
            ms.z  = a2[u].z * f * s2.z; ms.w  = a2[u].w * f * s2.w;

            red4(ns_acc + (size_t)dst[u] * H + 4 * lane, ms);

            float ux = ediff[3 * e]     * inv[u];
            float uy = ediff[3 * e + 1] * inv[u];
            float uz = ediff[3 * e + 2] * inv[u];
            const float4* nv4 = (const float4*)(nv_r + (size_t)src[u] * 384);
            float4 v0 = nv4[lane], v1 = nv4[32 + lane], v2 = nv4[64 + lane];
            float4 m0, m1, m2;
            m0.x = v0.x * gsv.x + ux * gev.x; m0.y = v0.y * gsv.y + ux * gev.y;
            m0.z = v0.z * gsv.z + ux * gev.z; m0.w = v0.w * gsv.w + ux * gev.w;
            m1.x = v1.x * gsv.x + uy * gev.x; m1.y = v1.y * gsv.y + uy * gev.y;
            m1.z = v1.z * gsv.z + uy * gev.z; m1.w = v1.w * gsv.w + uy * gev.w;
            m2.x = v2.x * gsv.x + uz * gev.x; m2.y = v2.y * gsv.y + uz * gev.y;
            m2.z = v2.z * gsv.z + uz * gev.z; m2.w = v2.w * gsv.w + uz * gev.w;
            float* base = nv_acc + (size_t)dst[u] * 384 + 4 * lane;
            red4(base,       m0);
            red4(base + 128, m1);
            red4(base + 256, m2);
        }
    }
}

// ---------------- Vv norm + concat into mlp_in ----------------
__global__ void norm_kernel() {
    int i = blockIdx.x * blockDim.x + threadIdx.x;
    if (i >= N_NODES * H) return;
    int n = i >> 7, h = i & 127;
    size_t base = (size_t)n * 384 + h;
    float v0 = g_Vv[base], v1 = g_Vv[base + 128], v2 = g_Vv[base + 256];
    g_mlpin[(size_t)n * 256 + h]       = sqrtf(v0 * v0 + v1 * v1 + v2 * v2);
    g_mlpin[(size_t)n * 256 + 128 + h] = g_ns[i];
}

// ---------------- gated update: ns += a_sv*<Uv,Vv> + a_ss; nv += a_vv*Uv ----------------
__global__ void update_kernel() {
    int i = blockIdx.x * blockDim.x + threadIdx.x;
    if (i >= N_NODES * H) return;
    int n = i >> 7, h = i & 127;
    const float* mo = g_big + (size_t)n * 384;
    float a_vv = mo[h], a_sv = mo[128 + h], a_ss = mo[256 + h];
    size_t base = (size_t)n * 384 + h;
    float dot = 0.0f;
#pragma unroll
    for (int d = 0; d < 3; d++) {
        float u = g_Uv[base + d * 128];
        float v = g_Vv[base + d * 128];
        dot = fmaf(u, v, dot);
        float nvnew = g_nvB[base + d * 128] + a_vv * u;
        g_nvA[base + d * 128] = nvnew;   // keep both buffers identical
        g_nvB[base + d * 128] = nvnew;
    }
    g_ns[i] += a_sv * dot + a_ss;
}

// ---------------- host launch ----------------
static void gemm(const float* A, const float* B, const float* bias, float* C,
                 int M, int N, int K, bool silu) {
    dim3 grid(N / 64, (M + 127) / 128);
    if (silu) sgemm_kernel<true><<<grid, 256>>>(A, B, bias, C, M, N, K);
    else      sgemm_kernel<false><<<grid, 256>>>(A, B, bias, C, M, N, K);
}

extern "C" void kernel_launch(void* const* d_in, const int* in_sizes, int n_in,
                              void* d_out, int out_size) {
    const int*   z            = (const int*)d_in[0];
    const int*   edge         = (const int*)d_in[1];
    const float* edge_diff    = (const float*)d_in[2];
    const float* edge_dist    = (const float*)d_in[3];
    const float* embed        = (const float*)d_in[4];
    const float* msg_filter_w = (const float*)d_in[5];   // 3 x 20 x 384
    const float* msg_filter_b = (const float*)d_in[6];   // 3 x 384
    const float* msg_w1       = (const float*)d_in[7];   // 3 x 128 x 128
    const float* msg_b1       = (const float*)d_in[8];
    const float* msg_w2       = (const float*)d_in[9];   // 3 x 128 x 384
    const float* msg_b2       = (const float*)d_in[10];
    const float* upd_U_w      = (const float*)d_in[11];
    const float* upd_U_b      = (const float*)d_in[12];
    const float* upd_V_w      = (const float*)d_in[13];
    const float* upd_V_b      = (const float*)d_in[14];
    const float* upd_w1       = (const float*)d_in[15];  // 3 x 256 x 128
    const float* upd_b1       = (const float*)d_in[16];
    const float* upd_w2       = (const float*)d_in[17];  // 3 x 128 x 384
    const float* upd_b2       = (const float*)d_in[18];
    const float* ro_w1        = (const float*)d_in[19];
    const float* ro_b1        = (const float*)d_in[20];
    const float* ro_w2        = (const float*)d_in[21];
    const float* ro_b2        = (const float*)d_in[22];
    float* out = (float*)d_out;

    float *ns, *nvA, *nvB, *hidden, *big, *Uv, *Vv, *mlpin;
    cudaGetSymbolAddress((void**)&ns,     g_ns);
    cudaGetSymbolAddress((void**)&nvA,    g_nvA);
    cudaGetSymbolAddress((void**)&nvB,    g_nvB);
    cudaGetSymbolAddress((void**)&hidden, g_hidden);
    cudaGetSymbolAddress((void**)&big,    g_big);
    cudaGetSymbolAddress((void**)&Uv,     g_Uv);
    cudaGetSymbolAddress((void**)&Vv,     g_Vv);
    cudaGetSymbolAddress((void**)&mlpin,  g_mlpin);

    init_kernel<<<(N_NODES * 3 * H + 255) / 256, 256>>>(z, embed);

    for (int l = 0; l < 3; l++) {
        // message MLP: scalar_out = silu(ns @ w1 + b1) @ w2 + b2
        gemm(ns, msg_w1 + (size_t)l * 128 * 128, msg_b1 + l * 128, hidden,
             N_NODES, 128, 128, true);
        gemm(hidden, msg_w2 + (size_t)l * 128 * 384, msg_b2 + l * 384, big,
             N_NODES, 384, 128, false);
        // edge messages + scatter-add aggregation (reads nvA, reduces into nvB)
        edge_kernel<<<1184, 256>>>(edge, edge_diff, edge_dist,
                                   msg_filter_w + (size_t)l * 20 * 384,
                                   msg_filter_b + l * 384,
                                   big, nvA, ns, nvB);
        // update block
        gemm(nvB, upd_U_w + (size_t)l * 128 * 128, upd_U_b + l * 128, Uv,
             N_NODES * 3, 128, 128, false);
        gemm(nvB, upd_V_w + (size_t)l * 128 * 128, upd_V_b + l * 128, Vv,
             N_NODES * 3, 128, 128, false);
        norm_kernel<<<(N_NODES * H + 255) / 256, 256>>>();
        gemm(mlpin, upd_w1 + (size_t)l * 256 * 128, upd_b1 + l * 128, hidden,
             N_NODES, 128, 256, true);
        gemm(hidden, upd_w2 + (size_t)l * 128 * 384, upd_b2 + l * 384, big,
             N_NODES, 384, 128, false);
        update_kernel<<<(N_NODES * H + 255) / 256, 256>>>();
    }

    // readout
    gemm(ns, ro_w1, ro_b1, hidden, N_NODES, 128, 128, true);
    gemm(hidden, ro_w2, ro_b2, out, N_NODES, 128, 128, false);
}

// round 3
// speedup vs baseline: 1.1087x; 1.1087x over previous
#include <cuda_runtime.h>
#include <cuda_bf16.h>
#include <math.h>

#define N_NODES 10000
#define N_EDGES 160000
#define H 128
#define E_RBF 20
#define CUTOFF 5.0f
#define PI_F 3.14159265358979f

typedef unsigned long long u64;

// ---------------- scratch (static device arrays; no allocation) ----------------
__device__ float g_ns[N_NODES * H];
__device__ float g_nvA[N_NODES * 3 * H];
__device__ float g_nvB[N_NODES * 3 * H];
__device__ float g_hidden[N_NODES * H];
__device__ float g_big[N_NODES * 3 * H];       // scalar_out / mlp_out (N x 384)
__device__ float g_UV[N_NODES * 3 * 256];      // fused [Uv | Vv] (30000 x 256)
__device__ float g_mlpin[N_NODES * 2 * H];
__device__ float g_UVw[3 * 128 * 256];         // packed [U_w | V_w] per layer
__device__ float g_UVb[3 * 256];

// ---------------- f32x2 helpers ----------------
__device__ __forceinline__ u64 pack2(float x, float y) {
    u64 r; asm("mov.b64 %0,{%1,%2};" : "=l"(r) : "f"(x), "f"(y)); return r;
}
__device__ __forceinline__ void unpack2(u64 v, float& x, float& y) {
    asm("mov.b64 {%0,%1},%2;" : "=f"(x), "=f"(y) : "l"(v));
}
__device__ __forceinline__ u64 fma2(u64 a, u64 b, u64 c) {
    u64 d; asm("fma.rn.f32x2 %0,%1,%2,%3;" : "=l"(d) : "l"(a), "l"(b), "l"(c)); return d;
}
__device__ __forceinline__ u64 mul2(u64 a, u64 b) {
    u64 d; asm("mul.rn.f32x2 %0,%1,%2;" : "=l"(d) : "l"(a), "l"(b)); return d;
}
__device__ __forceinline__ void red4(float* p, float x, float y, float z, float w) {
    asm volatile("red.global.add.v4.f32 [%0], {%1,%2,%3,%4};"
                 :: "l"(p), "f"(x), "f"(y), "f"(z), "f"(w) : "memory");
}
__device__ __forceinline__ float silu_f(float x) { return x / (1.0f + expf(-x)); }

// ---------------- init ----------------
__global__ void init_kernel(const int* __restrict__ z, const float* __restrict__ embed) {
    int i = blockIdx.x * blockDim.x + threadIdx.x;
    if (i >= N_NODES * 3 * H) return;
    g_nvA[i] = 0.0f;
    g_nvB[i] = 0.0f;
    if (i < N_NODES * H) {
        int n = i >> 7, h = i & 127;
        g_ns[i] = embed[z[n] * H + h];
    }
}

// ---------------- pack [U_w | V_w] for all 3 layers ----------------
__global__ void pack_uv_kernel(const float* __restrict__ Uw, const float* __restrict__ Ub,
                               const float* __restrict__ Vw, const float* __restrict__ Vb) {
    int i = blockIdx.x * blockDim.x + threadIdx.x;
    if (i < 3 * 128 * 256) {
        int l = i / (128 * 256), r = (i / 256) & 127, c = i & 255;
        g_UVw[i] = (c < 128) ? Uw[(size_t)l * 16384 + r * 128 + c]
                             : Vw[(size_t)l * 16384 + r * 128 + (c - 128)];
    }
    if (i < 3 * 256) {
        int l = i / 256, c = i & 255;
        g_UVb[i] = (c < 128) ? Ub[l * 128 + c] : Vb[l * 128 + (c - 128)];
    }
}

// ---------------- f32x2 tiled GEMM: C = act(A[MxK] @ B[KxN] + bias) ----------------
// BN=128, BK=8, 256 threads. BM=128 (TM=8) or BM=64 (TM=4). Double-buffered smem.
template<int BM, int TM, bool SILU>
__global__ __launch_bounds__(256)
void sgemm2(const float* __restrict__ A, const float* __restrict__ B,
            const float* __restrict__ bias, float* __restrict__ C,
            int M, int N, int K) {
    __shared__ float As[2][8][BM];
    __shared__ float Bs[2][8][128];
    const int t  = threadIdx.x;
    const int m0 = blockIdx.y * BM;
    const int n0 = blockIdx.x * 128;
    const int tx = t & 15;
    const int ty = t >> 4;
    const int arow = t >> 1;
    const int ak   = (t & 1) * 4;
    const bool aact = (BM == 128) || (t < 128);
    const int bk = t >> 5;
    const int bc = (t & 31) * 4;

    u64 acc[TM][4];
#pragma unroll
    for (int i = 0; i < TM; i++)
#pragma unroll
        for (int j = 0; j < 4; j++) acc[i][j] = 0ULL;

    float4 va = make_float4(0.f, 0.f, 0.f, 0.f), vb;
    if (aact && m0 + arow < M) va = *(const float4*)(A + (size_t)(m0 + arow) * K + ak);
    vb = *(const float4*)(B + (size_t)bk * N + n0 + bc);
    if (aact) {
        As[0][ak + 0][arow] = va.x; As[0][ak + 1][arow] = va.y;
        As[0][ak + 2][arow] = va.z; As[0][ak + 3][arow] = va.w;
    }
    *(float4*)&Bs[0][bk][bc] = vb;
    __syncthreads();

    const int nk = K >> 3;
    for (int kt = 0; kt < nk; kt++) {
        const int s = kt & 1;
        if (kt + 1 < nk) {
            const int k0 = (kt + 1) << 3;
            va = make_float4(0.f, 0.f, 0.f, 0.f);
            if (aact && m0 + arow < M)
                va = *(const float4*)(A + (size_t)(m0 + arow) * K + k0 + ak);
            vb = *(const float4*)(B + (size_t)(k0 + bk) * N + n0 + bc);
        }
#pragma unroll
        for (int k = 0; k < 8; k++) {
            u64 bp[4];
            bp[0] = *(const u64*)&Bs[s][k][tx * 4];
            bp[1] = *(const u64*)&Bs[s][k][tx * 4 + 2];
            bp[2] = *(const u64*)&Bs[s][k][64 + tx * 4];
            bp[3] = *(const u64*)&Bs[s][k][64 + tx * 4 + 2];
            float av[TM];
            *(float4*)&av[0] = *(const float4*)&As[s][k][ty * 4];
            if (TM == 8) *(float4*)&av[4] = *(const float4*)&As[s][k][64 + ty * 4];
#pragma unroll
            for (int i = 0; i < TM; i++) {
                u64 ap = pack2(av[i], av[i]);
                acc[i][0] = fma2(ap, bp[0], acc[i][0]);
                acc[i][1] = fma2(ap, bp[1], acc[i][1]);
                acc[i][2] = fma2(ap, bp[2], acc[i][2]);
                acc[i][3] = fma2(ap, bp[3], acc[i][3]);
            }
        }
        if (kt + 1 < nk) {
            const int ss = s ^ 1;
            if (aact) {
                As[ss][ak + 0][arow] = va.x; As[ss][ak + 1][arow] = va.y;
                As[ss][ak + 2][arow] = va.z; As[ss][ak + 3][arow] = va.w;
            }
            *(float4*)&Bs[ss][bk][bc] = vb;
            __syncthreads();
        }
    }

    float4 bb0 = *(const float4*)&bias[n0 + tx * 4];
    float4 bb1 = *(const float4*)&bias[n0 + 64 + tx * 4];
#pragma unroll
    for (int i = 0; i < TM; i++) {
        int row = m0 + ((TM == 8) ? ((i < 4) ? (ty * 4 + i) : (64 + ty * 4 + i - 4))
                                  : (ty * 4 + i));
        if (row < M) {
            float c0, c1, c2, c3, c4, c5, c6, c7;
            unpack2(acc[i][0], c0, c1); unpack2(acc[i][1], c2, c3);
            unpack2(acc[i][2], c4, c5); unpack2(acc[i][3], c6, c7);
            c0 += bb0.x; c1 += bb0.y; c2 += bb0.z; c3 += bb0.w;
            c4 += bb1.x; c5 += bb1.y; c6 += bb1.z; c7 += bb1.w;
            if (SILU) {
                c0 = silu_f(c0); c1 = silu_f(c1); c2 = silu_f(c2); c3 = silu_f(c3);
                c4 = silu_f(c4); c5 = silu_f(c5); c6 = silu_f(c6); c7 = silu_f(c7);
            }
            *(float4*)(C + (size_t)row * N + n0 + tx * 4)      = make_float4(c0, c1, c2, c3);
            *(float4*)(C + (size_t)row * N + n0 + 64 + tx * 4) = make_float4(c4, c5, c6, c7);
        }
    }
}

// ---------------- edge message kernel: 4 edges per warp, f32x2 math ----------------
__global__ __launch_bounds__(256, 2)
void edge_kernel(const int* __restrict__ edge,
                 const float* __restrict__ ediff,
                 const float* __restrict__ edist,
                 const float* __restrict__ Wf,   // 20x384
                 const float* __restrict__ bf,   // 384
                 const float* __restrict__ so,   // N x 384 scalar_out
                 const float* __restrict__ nv_r, // N x 384 (read)
                 float* __restrict__ ns_acc,     // N x 128
                 float* __restrict__ nv_acc)     // N x 384
{
    __shared__ float sW[E_RBF * 384 + 384];
    for (int i = threadIdx.x; i < E_RBF * 384; i += blockDim.x) sW[i] = Wf[i];
    for (int i = threadIdx.x; i < 384; i += blockDim.x) sW[E_RBF * 384 + i] = bf[i];
    __syncthreads();
    const u64* sW2 = (const u64*)sW;
    const u64* sB2 = (const u64*)(sW + E_RBF * 384);

    const int lane = threadIdx.x & 31;
    const int warp = (blockIdx.x * blockDim.x + threadIdx.x) >> 5;
    const int nw   = (gridDim.x * blockDim.x) >> 5;
    const int l2   = lane * 2;

    for (int e0 = warp * 4; e0 < N_EDGES; e0 += nw * 4) {
        int dst[4], src[4];
        float inv[4], invf[4], sC[4], sP[4], c2[4];
        u64 a0a[4], a0b[4], a1a[4], a1b[4], a2a[4], a2b[4];
#pragma unroll
        for (int u = 0; u < 4; u++) {
            int e = e0 + u;
            int2 ed = *(const int2*)(edge + 2 * e);
            dst[u] = ed.x; src[u] = ed.y;
            float d = edist[e];
            float sn, cs;
            sincosf(d * (PI_F / CUTOFF), &sn, &cs);
            float fcv = (d < CUTOFF) ? 0.5f * (cs + 1.0f) : 0.0f;
            inv[u]  = 1.0f / d;
            invf[u] = inv[u] * fcv;
            sC[u] = sn; sP[u] = 0.0f; c2[u] = 2.0f * cs;
            u64 fcp = pack2(fcv, fcv);
            a0a[u] = mul2(sB2[l2],       fcp); a0b[u] = mul2(sB2[l2 + 1],       fcp);
            a1a[u] = mul2(sB2[64 + l2],  fcp); a1b[u] = mul2(sB2[64 + l2 + 1],  fcp);
            a2a[u] = mul2(sB2[128 + l2], fcp); a2b[u] = mul2(sB2[128 + l2 + 1], fcp);
        }
#pragma unroll 4
        for (int n = 0; n < E_RBF; n++) {
            const u64* wn = sW2 + n * 192 + l2;
            u64 w0a = wn[0],   w0b = wn[1];
            u64 w1a = wn[64],  w1b = wn[65];
            u64 w2a = wn[128], w2b = wn[129];
#pragma unroll
            for (int u = 0; u < 4; u++) {
                float r = sC[u] * invf[u];
                u64 rp = pack2(r, r);
                a0a[u] = fma2(rp, w0a, a0a[u]); a0b[u] = fma2(rp, w0b, a0b[u]);
                a1a[u] = fma2(rp, w1a, a1a[u]); a1b[u] = fma2(rp, w1b, a1b[u]);
                a2a[u] = fma2(rp, w2a, a2a[u]); a2b[u] = fma2(rp, w2b, a2b[u]);
                float tn = fmaf(c2[u], sC[u], -sP[u]);
                sP[u] = sC[u]; sC[u] = tn;
            }
        }
#pragma unroll
        for (int u = 0; u < 4; u++) {
            int e = e0 + u;
            const u64* so2 = (const u64*)(so + (size_t)src[u] * 384);
            u64 g0a = mul2(a0a[u], so2[l2]);       u64 g0b = mul2(a0b[u], so2[l2 + 1]);
            u64 g1a = mul2(a1a[u], so2[64 + l2]);  u64 g1b = mul2(a1b[u], so2[64 + l2 + 1]);
            u64 g2a = mul2(a2a[u], so2[128 + l2]); u64 g2b = mul2(a2b[u], so2[128 + l2 + 1]);
            float s0, s1, s2, s3;
            unpack2(g2a, s0, s1); unpack2(g2b, s2, s3);
            red4(ns_acc + (size_t)dst[u] * H + 4 * lane, s0, s1, s2, s3);

            float ux = ediff[3 * e]     * inv[u];
            float uy = ediff[3 * e + 1] * inv[u];
            float uz = ediff[3 * e + 2] * inv[u];
            const u64* nv2 = (const u64*)(nv_r + (size_t)src[u] * 384);
            float* base = nv_acc + (size_t)dst[u] * 384 + 4 * lane;
            {
                u64 up = pack2(ux, ux);
                u64 ma = fma2(nv2[l2],     g0a, mul2(up, g1a));
                u64 mb = fma2(nv2[l2 + 1], g0b, mul2(up, g1b));
                float m0, m1, m2, m3;
                unpack2(ma, m0, m1); unpack2(mb, m2, m3);
                red4(base, m0, m1, m2, m3);
            }
            {
                u64 up = pack2(uy, uy);
                u64 ma = fma2(nv2[64 + l2],     g0a, mul2(up, g1a));
                u64 mb = fma2(nv2[64 + l2 + 1], g0b, mul2(up, g1b));
                float m0, m1, m2, m3;
                unpack2(ma, m0, m1); unpack2(mb, m2, m3);
                red4(base + 128, m0, m1, m2, m3);
            }
            {
                u64 up = pack2(uz, uz);
                u64 ma = fma2(nv2[128 + l2],     g0a, mul2(up, g1a));
                u64 mb = fma2(nv2[128 + l2 + 1], g0b, mul2(up, g1b));
                float m0, m1, m2, m3;
                unpack2(ma, m0, m1); unpack2(mb, m2, m3);
                red4(base + 256, m0, m1, m2, m3);
            }
        }
    }
}

// ---------------- Vv norm + concat into mlp_in ----------------
__global__ void norm_kernel() {
    int i = blockIdx.x * blockDim.x + threadIdx.x;
    if (i >= N_NODES * H) return;
    int n = i >> 7, h = i & 127;
    size_t base = (size_t)(3 * n) * 256 + 128 + h;   // Vv columns
    float v0 = g_UV[base], v1 = g_UV[base + 256], v2 = g_UV[base + 512];
    g_mlpin[(size_t)n * 256 + h]       = sqrtf(v0 * v0 + v1 * v1 + v2 * v2);
    g_mlpin[(size_t)n * 256 + 128 + h] = g_ns[i];
}

// ---------------- gated update ----------------
__global__ void update_kernel() {
    int i = blockIdx.x * blockDim.x + threadIdx.x;
    if (i >= N_NODES * H) return;
    int n = i >> 7, h = i & 127;
    const float* mo = g_big + (size_t)n * 384;
    float a_vv = mo[h], a_sv = mo[128 + h], a_ss = mo[256 + h];
    size_t nvb = (size_t)n * 384 + h;
    size_t uvb = (size_t)(3 * n) * 256 + h;
    float dot = 0.0f;
#pragma unroll
    for (int d = 0; d < 3; d++) {
        float u = g_UV[uvb + d * 256];
        float v = g_UV[uvb + d * 256 + 128];
        dot = fmaf(u, v, dot);
        float nvnew = g_nvB[nvb + d * 128] + a_vv * u;
        g_nvA[nvb + d * 128] = nvnew;
        g_nvB[nvb + d * 128] = nvnew;
    }
    g_ns[i] += a_sv * dot + a_ss;
}

// ---------------- host launch ----------------
static void gemm(const float* A, const float* B, const float* bias, float* C,
                 int M, int N, int K, bool silu) {
    if (N == 128) {
        dim3 g(1, (M + 63) / 64);
        if (silu) sgemm2<64, 4, true><<<g, 256>>>(A, B, bias, C, M, N, K);
        else      sgemm2<64, 4, false><<<g, 256>>>(A, B, bias, C, M, N, K);
    } else {
        dim3 g(N / 128, (M + 127) / 128);
        if (silu) sgemm2<128, 8, true><<<g, 256>>>(A, B, bias, C, M, N, K);
        else      sgemm2<128, 8, false><<<g, 256>>>(A, B, bias, C, M, N, K);
    }
}

extern "C" void kernel_launch(void* const* d_in, const int* in_sizes, int n_in,
                              void* d_out, int out_size) {
    const int*   z            = (const int*)d_in[0];
    const int*   edge         = (const int*)d_in[1];
    const float* edge_diff    = (const float*)d_in[2];
    const float* edge_dist    = (const float*)d_in[3];
    const float* embed        = (const float*)d_in[4];
    const float* msg_filter_w = (const float*)d_in[5];
    const float* msg_filter_b = (const float*)d_in[6];
    const float* msg_w1       = (const float*)d_in[7];
    const float* msg_b1       = (const float*)d_in[8];
    const float* msg_w2       = (const float*)d_in[9];
    const float* msg_b2       = (const float*)d_in[10];
    const float* upd_U_w      = (const float*)d_in[11];
    const float* upd_U_b      = (const float*)d_in[12];
    const float* upd_V_w      = (const float*)d_in[13];
    const float* upd_V_b      = (const float*)d_in[14];
    const float* upd_w1       = (const float*)d_in[15];
    const float* upd_b1       = (const float*)d_in[16];
    const float* upd_w2       = (const float*)d_in[17];
    const float* upd_b2       = (const float*)d_in[18];
    const float* ro_w1        = (const float*)d_in[19];
    const float* ro_b1        = (const float*)d_in[20];
    const float* ro_w2        = (const float*)d_in[21];
    const float* ro_b2        = (const float*)d_in[22];
    float* out = (float*)d_out;

    float *ns, *nvA, *nvB, *hidden, *big, *UV, *mlpin, *UVw, *UVb;
    cudaGetSymbolAddress((void**)&ns,     g_ns);
    cudaGetSymbolAddress((void**)&nvA,    g_nvA);
    cudaGetSymbolAddress((void**)&nvB,    g_nvB);
    cudaGetSymbolAddress((void**)&hidden, g_hidden);
    cudaGetSymbolAddress((void**)&big,    g_big);
    cudaGetSymbolAddress((void**)&UV,     g_UV);
    cudaGetSymbolAddress((void**)&mlpin,  g_mlpin);
    cudaGetSymbolAddress((void**)&UVw,    g_UVw);
    cudaGetSymbolAddress((void**)&UVb,    g_UVb);

    init_kernel<<<(N_NODES * 3 * H + 255) / 256, 256>>>(z, embed);
    pack_uv_kernel<<<(3 * 128 * 256 + 255) / 256, 256>>>(upd_U_w, upd_U_b, upd_V_w, upd_V_b);

    for (int l = 0; l < 3; l++) {
        gemm(ns, msg_w1 + (size_t)l * 128 * 128, msg_b1 + l * 128, hidden,
             N_NODES, 128, 128, true);
        gemm(hidden, msg_w2 + (size_t)l * 128 * 384, msg_b2 + l * 384, big,
             N_NODES, 384, 128, false);
        edge_kernel<<<1184, 256>>>(edge, edge_diff, edge_dist,
                                   msg_filter_w + (size_t)l * 20 * 384,
                                   msg_filter_b + l * 384,
                                   big, nvA, ns, nvB);
        gemm(nvB, UVw + (size_t)l * 128 * 256, UVb + l * 256, UV,
             N_NODES * 3, 256, 128, false);
        norm_kernel<<<(N_NODES * H + 255) / 256, 256>>>();
        gemm(mlpin, upd_w1 + (size_t)l * 256 * 128, upd_b1 + l * 128, hidden,
             N_NODES, 128, 256, true);
        gemm(hidden, upd_w2 + (size_t)l * 128 * 384, upd_b2 + l * 384, big,
             N_NODES, 384, 128, false);
        update_kernel<<<(N_NODES * H + 255) / 256, 256>>>();
    }

    gemm(ns, ro_w1, ro_b1, hidden, N_NODES, 128, 128, true);
    gemm(hidden, ro_w2, ro_b2, out, N_NODES, 128, 128, false);
}

// round 4
// speedup vs baseline: 1.4604x; 1.3172x over previous
#include <cuda_runtime.h>
#include <cuda_bf16.h>
#include <math.h>

#define N_NODES 10000
#define N_EDGES 160000
#define H 128
#define E_RBF 20
#define CUTOFF 5.0f
#define PI_F 3.14159265358979f

typedef unsigned long long u64;
typedef unsigned int u32;

// ---------------- scratch ----------------
__device__ float g_ns[N_NODES * H];
__device__ float g_nvA[N_NODES * 3 * H];
__device__ float g_nvB[N_NODES * 3 * H];
__device__ float g_hidden[N_NODES * H];
__device__ float g_big[N_NODES * 3 * H];
__device__ float g_UV[N_NODES * 3 * 256];
__device__ float g_mlpin[N_NODES * 2 * H];
__device__ float g_UVw[3 * 128 * 256];
__device__ float g_UVb[3 * 256];

// ---------------- helpers ----------------
__device__ __forceinline__ u64 pack2(float x, float y) {
    u64 r; asm("mov.b64 %0,{%1,%2};" : "=l"(r) : "f"(x), "f"(y)); return r;
}
__device__ __forceinline__ void unpack2(u64 v, float& x, float& y) {
    asm("mov.b64 {%0,%1},%2;" : "=f"(x), "=f"(y) : "l"(v));
}
__device__ __forceinline__ u64 fma2(u64 a, u64 b, u64 c) {
    u64 d; asm("fma.rn.f32x2 %0,%1,%2,%3;" : "=l"(d) : "l"(a), "l"(b), "l"(c)); return d;
}
__device__ __forceinline__ u64 mul2(u64 a, u64 b) {
    u64 d; asm("mul.rn.f32x2 %0,%1,%2;" : "=l"(d) : "l"(a), "l"(b)); return d;
}
__device__ __forceinline__ void red4(float* p, float x, float y, float z, float w) {
    asm volatile("red.global.add.v4.f32 [%0], {%1,%2,%3,%4};"
                 :: "l"(p), "f"(x), "f"(y), "f"(z), "f"(w) : "memory");
}
__device__ __forceinline__ float silu_f(float x) { return x / (1.0f + expf(-x)); }
__device__ __forceinline__ float tf32rna(float x) {
    u32 r; asm("cvt.rna.tf32.f32 %0, %1;" : "=r"(r) : "f"(x));
    return __uint_as_float(r);
}

#define MMA_TF32(cc, aa, bb)                                                      \
    asm volatile("mma.sync.aligned.m16n8k8.row.col.f32.tf32.tf32.f32 "            \
                 "{%0,%1,%2,%3},{%4,%5,%6,%7},{%8,%9},{%0,%1,%2,%3};"             \
                 : "+f"((cc)[0]), "+f"((cc)[1]), "+f"((cc)[2]), "+f"((cc)[3])     \
                 : "r"((aa)[0]), "r"((aa)[1]), "r"((aa)[2]), "r"((aa)[3]),        \
                   "r"((bb)[0]), "r"((bb)[1]))

// ---------------- init ----------------
__global__ void init_kernel(const int* __restrict__ z, const float* __restrict__ embed) {
    int i = blockIdx.x * blockDim.x + threadIdx.x;
    if (i >= N_NODES * 3 * H) return;
    g_nvA[i] = 0.0f;
    g_nvB[i] = 0.0f;
    if (i < N_NODES * H) {
        int n = i >> 7, h = i & 127;
        g_ns[i] = embed[z[n] * H + h];
    }
}

// ---------------- pack [U_w | V_w] ----------------
__global__ void pack_uv_kernel(const float* __restrict__ Uw, const float* __restrict__ Ub,
                               const float* __restrict__ Vw, const float* __restrict__ Vb) {
    int i = blockIdx.x * blockDim.x + threadIdx.x;
    if (i < 3 * 128 * 256) {
        int l = i / (128 * 256), r = (i / 256) & 127, c = i & 255;
        g_UVw[i] = (c < 128) ? Uw[(size_t)l * 16384 + r * 128 + c]
                             : Vw[(size_t)l * 16384 + r * 128 + (c - 128)];
    }
    if (i < 3 * 256) {
        int l = i / 256, c = i & 255;
        g_UVb[i] = (c < 128) ? Ub[l * 128 + c] : Vb[l * 128 + (c - 128)];
    }
}

// ---------------- TF32 tensor-core GEMM: C = act(A[MxK] @ B[KxN] + bias) ----------------
// BM=128, BN=128, BK=16. 256 threads = 8 warps, each warp 64x32 (4x4 of m16n8k8).
// N % 128 == 0, K % 16 == 0. M guarded.
template<bool SILU>
__global__ __launch_bounds__(256)
void mma_gemm(const float* __restrict__ A, const float* __restrict__ B,
              const float* __restrict__ bias, float* __restrict__ C,
              int M, int N, int K) {
    __shared__ float As[2][128][20];   // padded: fragment reads conflict-free
    __shared__ float Bs[2][16][136];
    const int t    = threadIdx.x;
    const int w    = t >> 5, lane = t & 31;
    const int g    = lane >> 2, tg = lane & 3;
    const int wm   = (w & 1) * 64;
    const int wn   = (w >> 1) * 32;
    const int m0   = blockIdx.y * 128;
    const int n0   = blockIdx.x * 128;

    float c[4][4][4];
#pragma unroll
    for (int i = 0; i < 4; i++)
#pragma unroll
        for (int j = 0; j < 4; j++)
#pragma unroll
            for (int q = 0; q < 4; q++) c[i][j][q] = 0.0f;

    // per-thread tile-load geometry (2 float4 for A, 2 for B)
    const int as  = t * 2;
    const int ar0 = as >> 2,        ak0 = (as & 3) << 2;
    const int ar1 = (as + 1) >> 2,  ak1 = ((as + 1) & 3) << 2;
    const int bs  = t * 2;
    const int bk0 = bs >> 5,        bn0 = (bs & 31) << 2;
    const int bk1 = (bs + 1) >> 5,  bn1 = ((bs + 1) & 31) << 2;

    float4 va0, va1, vb0, vb1;
    const float4 z4 = make_float4(0.f, 0.f, 0.f, 0.f);

    // prefetch stage 0
    va0 = (m0 + ar0 < M) ? *(const float4*)(A + (size_t)(m0 + ar0) * K + ak0) : z4;
    va1 = (m0 + ar1 < M) ? *(const float4*)(A + (size_t)(m0 + ar1) * K + ak1) : z4;
    vb0 = *(const float4*)(B + (size_t)bk0 * N + n0 + bn0);
    vb1 = *(const float4*)(B + (size_t)bk1 * N + n0 + bn1);
    {
        float* p0 = &As[0][ar0][ak0];
        p0[0] = tf32rna(va0.x); p0[1] = tf32rna(va0.y); p0[2] = tf32rna(va0.z); p0[3] = tf32rna(va0.w);
        float* p1 = &As[0][ar1][ak1];
        p1[0] = tf32rna(va1.x); p1[1] = tf32rna(va1.y); p1[2] = tf32rna(va1.z); p1[3] = tf32rna(va1.w);
        float* q0 = &Bs[0][bk0][bn0];
        q0[0] = tf32rna(vb0.x); q0[1] = tf32rna(vb0.y); q0[2] = tf32rna(vb0.z); q0[3] = tf32rna(vb0.w);
        float* q1 = &Bs[0][bk1][bn1];
        q1[0] = tf32rna(vb1.x); q1[1] = tf32rna(vb1.y); q1[2] = tf32rna(vb1.z); q1[3] = tf32rna(vb1.w);
    }
    __syncthreads();

    const int nk = K >> 4;
    for (int kt = 0; kt < nk; kt++) {
        const int s = kt & 1;
        if (kt + 1 < nk) {
            const int k0 = (kt + 1) << 4;
            va0 = (m0 + ar0 < M) ? *(const float4*)(A + (size_t)(m0 + ar0) * K + k0 + ak0) : z4;
            va1 = (m0 + ar1 < M) ? *(const float4*)(A + (size_t)(m0 + ar1) * K + k0 + ak1) : z4;
            vb0 = *(const float4*)(B + (size_t)(k0 + bk0) * N + n0 + bn0);
            vb1 = *(const float4*)(B + (size_t)(k0 + bk1) * N + n0 + bn1);
        }
#pragma unroll
        for (int kk = 0; kk < 2; kk++) {
            const int kb = kk * 8;
            u32 a[4][4], b[4][2];
#pragma unroll
            for (int mt = 0; mt < 4; mt++) {
                const int r = wm + mt * 16 + g;
                a[mt][0] = __float_as_uint(As[s][r][kb + tg]);
                a[mt][1] = __float_as_uint(As[s][r + 8][kb + tg]);
                a[mt][2] = __float_as_uint(As[s][r][kb + tg + 4]);
                a[mt][3] = __float_as_uint(As[s][r + 8][kb + tg + 4]);
            }
#pragma unroll
            for (int nt = 0; nt < 4; nt++) {
                const int col = wn + nt * 8 + g;
                b[nt][0] = __float_as_uint(Bs[s][kb + tg][col]);
                b[nt][1] = __float_as_uint(Bs[s][kb + tg + 4][col]);
            }
#pragma unroll
            for (int mt = 0; mt < 4; mt++)
#pragma unroll
                for (int nt = 0; nt < 4; nt++)
                    MMA_TF32(c[mt][nt], a[mt], b[nt]);
        }
        if (kt + 1 < nk) {
            const int ss = s ^ 1;
            float* p0 = &As[ss][ar0][ak0];
            p0[0] = tf32rna(va0.x); p0[1] = tf32rna(va0.y); p0[2] = tf32rna(va0.z); p0[3] = tf32rna(va0.w);
            float* p1 = &As[ss][ar1][ak1];
            p1[0] = tf32rna(va1.x); p1[1] = tf32rna(va1.y); p1[2] = tf32rna(va1.z); p1[3] = tf32rna(va1.w);
            float* q0 = &Bs[ss][bk0][bn0];
            q0[0] = tf32rna(vb0.x); q0[1] = tf32rna(vb0.y); q0[2] = tf32rna(vb0.z); q0[3] = tf32rna(vb0.w);
            float* q1 = &Bs[ss][bk1][bn1];
            q1[0] = tf32rna(vb1.x); q1[1] = tf32rna(vb1.y); q1[2] = tf32rna(vb1.z); q1[3] = tf32rna(vb1.w);
            __syncthreads();
        }
    }

    // epilogue: bias (+SiLU), float2 stores
#pragma unroll
    for (int nt = 0; nt < 4; nt++) {
        const int col = n0 + wn + nt * 8 + 2 * tg;
        const float2 bb = *(const float2*)&bias[col];
#pragma unroll
        for (int mt = 0; mt < 4; mt++) {
            const int r0 = m0 + wm + mt * 16 + g;
            float v0 = c[mt][nt][0] + bb.x, v1 = c[mt][nt][1] + bb.y;
            float v2 = c[mt][nt][2] + bb.x, v3 = c[mt][nt][3] + bb.y;
            if (SILU) { v0 = silu_f(v0); v1 = silu_f(v1); v2 = silu_f(v2); v3 = silu_f(v3); }
            if (r0 < M)     *(float2*)(C + (size_t)r0 * N + col)       = make_float2(v0, v1);
            if (r0 + 8 < M) *(float2*)(C + (size_t)(r0 + 8) * N + col) = make_float2(v2, v3);
        }
    }
}

// ---------------- edge message kernel: 4 edges per warp, f32x2 math ----------------
__global__ __launch_bounds__(256, 2)
void edge_kernel(const int* __restrict__ edge,
                 const float* __restrict__ ediff,
                 const float* __restrict__ edist,
                 const float* __restrict__ Wf,
                 const float* __restrict__ bf,
                 const float* __restrict__ so,
                 const float* __restrict__ nv_r,
                 float* __restrict__ ns_acc,
                 float* __restrict__ nv_acc)
{
    __shared__ float sW[E_RBF * 384 + 384];
    for (int i = threadIdx.x; i < E_RBF * 384; i += blockDim.x) sW[i] = Wf[i];
    for (int i = threadIdx.x; i < 384; i += blockDim.x) sW[E_RBF * 384 + i] = bf[i];
    __syncthreads();
    const u64* sW2 = (const u64*)sW;
    const u64* sB2 = (const u64*)(sW + E_RBF * 384);

    const int lane = threadIdx.x & 31;
    const int warp = (blockIdx.x * blockDim.x + threadIdx.x) >> 5;
    const int nw   = (gridDim.x * blockDim.x) >> 5;
    const int l2   = lane * 2;

    for (int e0 = warp * 4; e0 < N_EDGES; e0 += nw * 4) {
        int dst[4], src[4];
        float inv[4], invf[4], sC[4], sP[4], c2[4];
        u64 a0a[4], a0b[4], a1a[4], a1b[4], a2a[4], a2b[4];
#pragma unroll
        for (int u = 0; u < 4; u++) {
            int e = e0 + u;
            int2 ed = *(const int2*)(edge + 2 * e);
            dst[u] = ed.x; src[u] = ed.y;
            float d = edist[e];
            float sn, cs;
            sincosf(d * (PI_F / CUTOFF), &sn, &cs);
            float fcv = (d < CUTOFF) ? 0.5f * (cs + 1.0f) : 0.0f;
            inv[u]  = 1.0f / d;
            invf[u] = inv[u] * fcv;
            sC[u] = sn; sP[u] = 0.0f; c2[u] = 2.0f * cs;
            u64 fcp = pack2(fcv, fcv);
            a0a[u] = mul2(sB2[l2],       fcp); a0b[u] = mul2(sB2[l2 + 1],       fcp);
            a1a[u] = mul2(sB2[64 + l2],  fcp); a1b[u] = mul2(sB2[64 + l2 + 1],  fcp);
            a2a[u] = mul2(sB2[128 + l2], fcp); a2b[u] = mul2(sB2[128 + l2 + 1], fcp);
        }
#pragma unroll 4
        for (int n = 0; n < E_RBF; n++) {
            const u64* wn = sW2 + n * 192 + l2;
            u64 w0a = wn[0],   w0b = wn[1];
            u64 w1a = wn[64],  w1b = wn[65];
            u64 w2a = wn[128], w2b = wn[129];
#pragma unroll
            for (int u = 0; u < 4; u++) {
                float r = sC[u] * invf[u];
                u64 rp = pack2(r, r);
                a0a[u] = fma2(rp, w0a, a0a[u]); a0b[u] = fma2(rp, w0b, a0b[u]);
                a1a[u] = fma2(rp, w1a, a1a[u]); a1b[u] = fma2(rp, w1b, a1b[u]);
                a2a[u] = fma2(rp, w2a, a2a[u]); a2b[u] = fma2(rp, w2b, a2b[u]);
                float tn = fmaf(c2[u], sC[u], -sP[u]);
                sP[u] = sC[u]; sC[u] = tn;
            }
        }
#pragma unroll
        for (int u = 0; u < 4; u++) {
            int e = e0 + u;
            const u64* so2 = (const u64*)(so + (size_t)src[u] * 384);
            u64 g0a = mul2(a0a[u], so2[l2]);       u64 g0b = mul2(a0b[u], so2[l2 + 1]);
            u64 g1a = mul2(a1a[u], so2[64 + l2]);  u64 g1b = mul2(a1b[u], so2[64 + l2 + 1]);
            u64 g2a = mul2(a2a[u], so2[128 + l2]); u64 g2b = mul2(a2b[u], so2[128 + l2 + 1]);
            float s0, s1, s2, s3;
            unpack2(g2a, s0, s1); unpack2(g2b, s2, s3);
            red4(ns_acc + (size_t)dst[u] * H + 4 * lane, s0, s1, s2, s3);

            float ux = ediff[3 * e]     * inv[u];
            float uy = ediff[3 * e + 1] * inv[u];
            float uz = ediff[3 * e + 2] * inv[u];
            const u64* nv2 = (const u64*)(nv_r + (size_t)src[u] * 384);
            float* base = nv_acc + (size_t)dst[u] * 384 + 4 * lane;
            {
                u64 up = pack2(ux, ux);
                u64 ma = fma2(nv2[l2],     g0a, mul2(up, g1a));
                u64 mb = fma2(nv2[l2 + 1], g0b, mul2(up, g1b));
                float m0, m1, m2, m3;
                unpack2(ma, m0, m1); unpack2(mb, m2, m3);
                red4(base, m0, m1, m2, m3);
            }
            {
                u64 up = pack2(uy, uy);
                u64 ma = fma2(nv2[64 + l2],     g0a, mul2(up, g1a));
                u64 mb = fma2(nv2[64 + l2 + 1], g0b, mul2(up, g1b));
                float m0, m1, m2, m3;
                unpack2(ma, m0, m1); unpack2(mb, m2, m3);
                red4(base + 128, m0, m1, m2, m3);
            }
            {
                u64 up = pack2(uz, uz);
                u64 ma = fma2(nv2[128 + l2],     g0a, mul2(up, g1a));
                u64 mb = fma2(nv2[128 + l2 + 1], g0b, mul2(up, g1b));
                float m0, m1, m2, m3;
                unpack2(ma, m0, m1); unpack2(mb, m2, m3);
                red4(base + 256, m0, m1, m2, m3);
            }
        }
    }
}

// ---------------- Vv norm + concat into mlp_in ----------------
__global__ void norm_kernel() {
    int i = blockIdx.x * blockDim.x + threadIdx.x;
    if (i >= N_NODES * H) return;
    int n = i >> 7, h = i & 127;
    size_t base = (size_t)(3 * n) * 256 + 128 + h;
    float v0 = g_UV[base], v1 = g_UV[base + 256], v2 = g_UV[base + 512];
    g_mlpin[(size_t)n * 256 + h]       = sqrtf(v0 * v0 + v1 * v1 + v2 * v2);
    g_mlpin[(size_t)n * 256 + 128 + h] = g_ns[i];
}

// ---------------- gated update ----------------
__global__ void update_kernel() {
    int i = blockIdx.x * blockDim.x + threadIdx.x;
    if (i >= N_NODES * H) return;
    int n = i >> 7, h = i & 127;
    const float* mo = g_big + (size_t)n * 384;
    float a_vv = mo[h], a_sv = mo[128 + h], a_ss = mo[256 + h];
    size_t nvb = (size_t)n * 384 + h;
    size_t uvb = (size_t)(3 * n) * 256 + h;
    float dot = 0.0f;
#pragma unroll
    for (int d = 0; d < 3; d++) {
        float u = g_UV[uvb + d * 256];
        float v = g_UV[uvb + d * 256 + 128];
        dot = fmaf(u, v, dot);
        float nvnew = g_nvB[nvb + d * 128] + a_vv * u;
        g_nvA[nvb + d * 128] = nvnew;
        g_nvB[nvb + d * 128] = nvnew;
    }
    g_ns[i] += a_sv * dot + a_ss;
}

// ---------------- host launch ----------------
static void gemm(const float* A, const float* B, const float* bias, float* C,
                 int M, int N, int K, bool silu) {
    dim3 g(N / 128, (M + 127) / 128);
    if (silu) mma_gemm<true><<<g, 256>>>(A, B, bias, C, M, N, K);
    else      mma_gemm<false><<<g, 256>>>(A, B, bias, C, M, N, K);
}

extern "C" void kernel_launch(void* const* d_in, const int* in_sizes, int n_in,
                              void* d_out, int out_size) {
    const int*   z            = (const int*)d_in[0];
    const int*   edge         = (const int*)d_in[1];
    const float* edge_diff    = (const float*)d_in[2];
    const float* edge_dist    = (const float*)d_in[3];
    const float* embed        = (const float*)d_in[4];
    const float* msg_filter_w = (const float*)d_in[5];
    const float* msg_filter_b = (const float*)d_in[6];
    const float* msg_w1       = (const float*)d_in[7];
    const float* msg_b1       = (const float*)d_in[8];
    const float* msg_w2       = (const float*)d_in[9];
    const float* msg_b2       = (const float*)d_in[10];
    const float* upd_U_w      = (const float*)d_in[11];
    const float* upd_U_b      = (const float*)d_in[12];
    const float* upd_V_w      = (const float*)d_in[13];
    const float* upd_V_b      = (const float*)d_in[14];
    const float* upd_w1       = (const float*)d_in[15];
    const float* upd_b1       = (const float*)d_in[16];
    const float* upd_w2       = (const float*)d_in[17];
    const float* upd_b2       = (const float*)d_in[18];
    const float* ro_w1        = (const float*)d_in[19];
    const float* ro_b1        = (const float*)d_in[20];
    const float* ro_w2        = (const float*)d_in[21];
    const float* ro_b2        = (const float*)d_in[22];
    float* out = (float*)d_out;

    float *ns, *nvA, *nvB, *hidden, *big, *UV, *mlpin, *UVw, *UVb;
    cudaGetSymbolAddress((void**)&ns,     g_ns);
    cudaGetSymbolAddress((void**)&nvA,    g_nvA);
    cudaGetSymbolAddress((void**)&nvB,    g_nvB);
    cudaGetSymbolAddress((void**)&hidden, g_hidden);
    cudaGetSymbolAddress((void**)&big,    g_big);
    cudaGetSymbolAddress((void**)&UV,     g_UV);
    cudaGetSymbolAddress((void**)&mlpin,  g_mlpin);
    cudaGetSymbolAddress((void**)&UVw,    g_UVw);
    cudaGetSymbolAddress((void**)&UVb,    g_UVb);

    init_kernel<<<(N_NODES * 3 * H + 255) / 256, 256>>>(z, embed);
    pack_uv_kernel<<<(3 * 128 * 256 + 255) / 256, 256>>>(upd_U_w, upd_U_b, upd_V_w, upd_V_b);

    for (int l = 0; l < 3; l++) {
        gemm(ns, msg_w1 + (size_t)l * 128 * 128, msg_b1 + l * 128, hidden,
             N_NODES, 128, 128, true);
        gemm(hidden, msg_w2 + (size_t)l * 128 * 384, msg_b2 + l * 384, big,
             N_NODES, 384, 128, false);
        edge_kernel<<<1184, 256>>>(edge, edge_diff, edge_dist,
                                   msg_filter_w + (size_t)l * 20 * 384,
                                   msg_filter_b + l * 384,
                                   big, nvA, ns, nvB);
        gemm(nvB, UVw + (size_t)l * 128 * 256, UVb + l * 256, UV,
             N_NODES * 3, 256, 128, false);
        norm_kernel<<<(N_NODES * H + 255) / 256, 256>>>();
        gemm(mlpin, upd_w1 + (size_t)l * 256 * 128, upd_b1 + l * 128, hidden,
             N_NODES, 128, 256, true);
        gemm(hidden, upd_w2 + (size_t)l * 128 * 384, upd_b2 + l * 384, big,
             N_NODES, 384, 128, false);
        update_kernel<<<(N_NODES * H + 255) / 256, 256>>>();
    }

    gemm(ns, ro_w1, ro_b1, hidden, N_NODES, 128, 128, true);
    gemm(hidden, ro_w2, ro_b2, out, N_NODES, 128, 128, false);
}